// round 4
// baseline (speedup 1.0000x reference)
#include <cuda_runtime.h>
#include <cuda_bf16.h>
#include <cstdint>

// Problem constants
#define BB 4
#define NN 16384
#define EE 65536
#define CC 256
#define MM 64

// Derived
#define K1_ROWS 128
#define K1_GRID (BB*NN/K1_ROWS)          // 512
#define K4_ROWS 128
#define K4_GRID (BB*EE/K4_ROWS)          // 2048
#define SXS 260                          // padded x-tile stride (words, 16B-aligned rows)
#define LTS 68                           // padded logit-tile stride (words, 16B-aligned m-quads)
#define ESS 65                           // padded edge-tile stride
#define JSPLIT 8                         // Tpart reduction split factor

// ---------- packed fp32x2 helpers (FFMA2 — ptxas never emits this from C++) ----
__device__ __forceinline__ unsigned long long pk2(float lo, float hi) {
    unsigned long long r;
    asm("mov.b64 %0, {%1, %2};" : "=l"(r) : "f"(lo), "f"(hi));
    return r;
}
__device__ __forceinline__ void fma2(unsigned long long& d, unsigned long long a,
                                     unsigned long long b) {
    asm("fma.rn.f32x2 %0, %1, %2, %0;" : "+l"(d) : "l"(a), "l"(b));
}
__device__ __forceinline__ float2 up2(unsigned long long v) {
    float2 r;
    asm("mov.b64 {%0, %1}, %2;" : "=f"(r.x), "=f"(r.y) : "l"(v));
    return r;
}

// -------- device scratch (no allocations allowed) --------
__device__ __align__(16) float g_Wc[CC*MM];            // (W_x @ W_slice)/t_x  [C,M]
__device__ __align__(16) float g_bc[MM];               // ((b_x+ph_x)@W_slice + b_slice)/t_x
__device__ __align__(16) float g_We[MM*MM];            // W_eslice[k,m]/t_e[k]
__device__ __align__(16) float g_cedge[CC];            // b_fedge + ph_edge
__device__ __align__(16) float g_Tpart[(size_t)K1_GRID*MM*CC]; // 32MB partials of sw^T x
__device__ __align__(16) float g_T2[(size_t)JSPLIT*BB*MM*CC];  // 2MB stage-1 reduced
__device__ __align__(16) float g_npart[K1_GRID*MM];    // per-block column sums of sw
__device__ __align__(16) float g_epart[(size_t)K4_GRID*2*MM];  // per-block [enorm(64), es1(64)]

// ======================= K0: prep ===========================
__global__ void __launch_bounds__(256) k_prep(
    const float* __restrict__ W_x,  const float* __restrict__ b_x,
    const float* __restrict__ W_slice, const float* __restrict__ b_slice,
    const float* __restrict__ temp_x, const float* __restrict__ ph_x,
    const float* __restrict__ b_fedge, const float* __restrict__ temp_edge,
    const float* __restrict__ W_eslice, const float* __restrict__ ph_edge)
{
    int tid = threadIdx.x;
    int mb  = blockIdx.x;
    if (mb < MM) {
        __shared__ float wsl[CC];
        __shared__ float red[256];
        wsl[tid] = W_slice[tid*MM + mb];
        __syncthreads();
        float tx = fminf(fmaxf(temp_x[mb], 0.01f), 5.0f);
        float itx = 1.0f / tx;
        // Wc column mb (float4 row loads, one sector per 4 k)
        const float4* wxr = (const float4*)(W_x + (size_t)tid*CC);
        float a = 0.f;
        #pragma unroll 8
        for (int k = 0; k < CC/4; k++) {
            float4 w = wxr[k];
            float4 sv = *(const float4*)&wsl[k*4];
            a = fmaf(w.x, sv.x, a); a = fmaf(w.y, sv.y, a);
            a = fmaf(w.z, sv.z, a); a = fmaf(w.w, sv.w, a);
        }
        g_Wc[tid*MM + mb] = a * itx;
        // bc[mb]
        red[tid] = (b_x[tid] + ph_x[tid]) * wsl[tid];
        __syncthreads();
        for (int s = 128; s > 0; s >>= 1) {
            if (tid < s) red[tid] += red[tid + s];
            __syncthreads();
        }
        if (tid == 0) g_bc[mb] = (red[0] + b_slice[mb]) * itx;
        // We column mb (rows scaled by 1/t_e[k])
        if (tid < MM) {
            float te = fminf(fmaxf(temp_edge[tid], 0.01f), 5.0f);
            g_We[tid*MM + mb] = W_eslice[tid*MM + mb] / te;
        }
    } else {
        g_cedge[tid] = b_fedge[tid] + ph_edge[tid];
    }
}

// ======================= K1: node path (512 threads) ======================
// Per block: 128 rows. split-C logits GEMM -> combine -> softmax -> write
// slice_weight, column sums -> g_npart, partial sw^T x -> g_Tpart (16 warps).
__global__ void __launch_bounds__(512) k_node(const float* __restrict__ x,
                                              float* __restrict__ out)
{
    extern __shared__ float sm[];
    float* sWc = sm;                 // 16384 floats (64KB)
    float* sx  = sm + CC*MM;         // 128*260 floats
    float* lt  = sm;                 // alias of sWc region after GEMM (128*68 = 8704)

    int tid = threadIdx.x;
    int r0g = blockIdx.x * K1_ROWS;

    // load Wc (4096 float4 over 512 threads)
    {
        const float4* wg = (const float4*)g_Wc;
        float4* ws = (float4*)sWc;
        #pragma unroll
        for (int i = 0; i < 8; i++) ws[tid + i*512] = wg[tid + i*512];
    }
    // load x tile (8192 float4)
    {
        const float4* xg = (const float4*)(x + (size_t)r0g*CC);
        #pragma unroll
        for (int i = 0; i < 16; i++) {
            int idx4 = i*512 + tid;
            float4 v = xg[idx4];
            int row = idx4 >> 6, c = (idx4 & 63) * 4;
            *(float4*)&sx[row*SXS + c] = v;
        }
    }
    __syncthreads();

    // ---- logits GEMM: split-C 2-way; per thread 4 rows x 8 m over 128 c ----
    int grp = tid >> 8;              // 0/1 -> c half
    int t   = tid & 255;
    int m0  = (t & 7) * 8;
    int rb  = (t >> 3) * 4;
    int c0  = grp * 128;
    unsigned long long acc[4][4] = {};

    #pragma unroll 2
    for (int cc4 = 0; cc4 < 128; cc4 += 4) {
        int c = c0 + cc4;
        ulonglong2 wa0 = *(const ulonglong2*)&sWc[(c+0)*MM + m0];
        ulonglong2 wb0 = *(const ulonglong2*)&sWc[(c+0)*MM + m0 + 4];
        ulonglong2 wa1 = *(const ulonglong2*)&sWc[(c+1)*MM + m0];
        ulonglong2 wb1 = *(const ulonglong2*)&sWc[(c+1)*MM + m0 + 4];
        ulonglong2 wa2 = *(const ulonglong2*)&sWc[(c+2)*MM + m0];
        ulonglong2 wb2 = *(const ulonglong2*)&sWc[(c+2)*MM + m0 + 4];
        ulonglong2 wa3 = *(const ulonglong2*)&sWc[(c+3)*MM + m0];
        ulonglong2 wb3 = *(const ulonglong2*)&sWc[(c+3)*MM + m0 + 4];
        #pragma unroll
        for (int i = 0; i < 4; i++) {
            float4 xv = *(const float4*)&sx[(rb + i)*SXS + c];
            unsigned long long xp;
            xp = pk2(xv.x, xv.x);
            fma2(acc[i][0], xp, wa0.x); fma2(acc[i][1], xp, wa0.y);
            fma2(acc[i][2], xp, wb0.x); fma2(acc[i][3], xp, wb0.y);
            xp = pk2(xv.y, xv.y);
            fma2(acc[i][0], xp, wa1.x); fma2(acc[i][1], xp, wa1.y);
            fma2(acc[i][2], xp, wb1.x); fma2(acc[i][3], xp, wb1.y);
            xp = pk2(xv.z, xv.z);
            fma2(acc[i][0], xp, wa2.x); fma2(acc[i][1], xp, wa2.y);
            fma2(acc[i][2], xp, wb2.x); fma2(acc[i][3], xp, wb2.y);
            xp = pk2(xv.w, xv.w);
            fma2(acc[i][0], xp, wa3.x); fma2(acc[i][1], xp, wa3.y);
            fma2(acc[i][2], xp, wb3.x); fma2(acc[i][3], xp, wb3.y);
        }
    }
    __syncthreads();   // all sWc reads done; region becomes lt

    // combine: grp1 writes partials, grp0 adds + bias
    if (grp == 1) {
        #pragma unroll
        for (int i = 0; i < 4; i++) {
            float2 a0 = up2(acc[i][0]), a1 = up2(acc[i][1]);
            float2 a2v = up2(acc[i][2]), a3 = up2(acc[i][3]);
            float* d = &lt[(rb + i)*LTS + m0];
            *(float4*)&d[0] = make_float4(a0.x, a0.y, a1.x, a1.y);
            *(float4*)&d[4] = make_float4(a2v.x, a2v.y, a3.x, a3.y);
        }
    }
    __syncthreads();
    if (grp == 0) {
        float4 be0 = *(const float4*)&g_bc[m0];
        float4 be1 = *(const float4*)&g_bc[m0 + 4];
        #pragma unroll
        for (int i = 0; i < 4; i++) {
            float2 a0 = up2(acc[i][0]), a1 = up2(acc[i][1]);
            float2 a2v = up2(acc[i][2]), a3 = up2(acc[i][3]);
            float* d = &lt[(rb + i)*LTS + m0];
            float4 p0 = *(const float4*)&d[0];
            float4 p1 = *(const float4*)&d[4];
            *(float4*)&d[0] = make_float4(a0.x + p0.x + be0.x, a0.y + p0.y + be0.y,
                                          a1.x + p0.z + be0.z, a1.y + p0.w + be0.w);
            *(float4*)&d[4] = make_float4(a2v.x + p1.x + be1.x, a2v.y + p1.y + be1.y,
                                          a3.x + p1.z + be1.z, a3.y + p1.w + be1.w);
        }
    }
    __syncthreads();

    // ---- softmax per row (threads 0..127), write slice_weight ----
    if (tid < K1_ROWS) {
        float* row = &lt[tid*LTS];
        float mx = -1e30f;
        #pragma unroll
        for (int m = 0; m < MM; m++) mx = fmaxf(mx, row[m]);
        float s = 0.f;
        #pragma unroll
        for (int m = 0; m < MM; m++) {
            float e = __expf(row[m] - mx);
            row[m] = e; s += e;
        }
        float inv = 1.f / s;
        float4* og = (float4*)(out + (size_t)BB*MM*CC + (size_t)(r0g + tid)*MM);
        #pragma unroll
        for (int m4 = 0; m4 < 16; m4++) {
            float4 v;
            v.x = row[m4*4+0]*inv; v.y = row[m4*4+1]*inv;
            v.z = row[m4*4+2]*inv; v.w = row[m4*4+3]*inv;
            og[m4] = v;
            row[m4*4+0]=v.x; row[m4*4+1]=v.y; row[m4*4+2]=v.z; row[m4*4+3]=v.w;
        }
    }
    __syncthreads();

    // column sums of sw -> npart
    if (tid < MM) {
        float s = 0.f;
        #pragma unroll 4
        for (int r = 0; r < K1_ROWS; r++) s += lt[r*LTS + tid];
        g_npart[blockIdx.x*MM + tid] = s;
    }

    // ---- partial T = sw^T @ x  (64 x 256), 16 warps x 4 m-rows ----
    int w = tid >> 5, lane = tid & 31;
    int mb4 = w * 4;
    float* tp = g_Tpart + (size_t)blockIdx.x * (MM*CC);
    #pragma unroll
    for (int q = 0; q < 2; q++) {
        unsigned long long a2[2][4] = {};   // [m-pair][k]
        for (int r = 0; r < K1_ROWS; r++) {
            ulonglong2 s0 = *(const ulonglong2*)&lt[r*LTS + mb4];  // (m0,m1),(m2,m3)
            #pragma unroll
            for (int k = 0; k < 4; k++) {
                float xv = sx[r*SXS + q*128 + k*32 + lane];
                unsigned long long xp = pk2(xv, xv);
                fma2(a2[0][k], s0.x, xp);
                fma2(a2[1][k], s0.y, xp);
            }
        }
        #pragma unroll
        for (int jp = 0; jp < 2; jp++)
            #pragma unroll
            for (int k = 0; k < 4; k++) {
                float2 v = up2(a2[jp][k]);
                int cc = q*128 + k*32 + lane;
                tp[(mb4 + jp*2    )*CC + cc] = v.x;
                tp[(mb4 + jp*2 + 1)*CC + cc] = v.y;
            }
    }
}

// ======================= K4: edge path ======================
__global__ void __launch_bounds__(256) k_edge(const float* __restrict__ edge_attr,
                                              const int*   __restrict__ edge_idx,
                                              const float* __restrict__ b_eslice,
                                              const float* __restrict__ out_ro)
{
    extern __shared__ float sm[];
    float* sWe = sm;                  // 4096
    float* ss  = sm + MM*MM;          // 128*65
    float* sa  = ss + K4_ROWS*ESS;    // 128

    int tid = threadIdx.x;
    int eb  = blockIdx.x * K4_ROWS;
    int b   = eb >> 16;               // E = 65536
    const float* swb = out_ro + (size_t)BB*MM*CC + (size_t)b*NN*MM;

    // load We
    {
        const float4* s = (const float4*)g_We;
        float4* d = (float4*)sWe;
        #pragma unroll
        for (int i = 0; i < 4; i++) d[tid + i*256] = s[tid + i*256];
    }
    if (tid < K4_ROWS) sa[tid] = edge_attr[eb + tid];

    // gather + sum (2 threads per edge)
    {
        int r = tid >> 1, half = tid & 1;
        int i0 = edge_idx[(size_t)(eb + r)*2 + 0];
        int i1 = edge_idx[(size_t)(eb + r)*2 + 1];
        const float4* p0 = (const float4*)(swb + (size_t)i0*MM) + half*8;
        const float4* p1 = (const float4*)(swb + (size_t)i1*MM) + half*8;
        float* d = &ss[r*ESS + half*32];
        #pragma unroll
        for (int j = 0; j < 8; j++) {
            float4 a = p0[j], c = p1[j];
            d[j*4+0] = a.x + c.x; d[j*4+1] = a.y + c.y;
            d[j*4+2] = a.z + c.z; d[j*4+3] = a.w + c.w;
        }
    }
    __syncthreads();

    // GEMM: each thread 4 rows x 8 m, packed m-pairs
    int tm = tid & 7, trr = tid >> 3;
    int m0 = tm * 8, r0 = trr * 4;
    unsigned long long acc[4][4] = {};

    #pragma unroll 4
    for (int k = 0; k < MM; k++) {
        ulonglong2 w0 = *(const ulonglong2*)&sWe[k*MM + m0];
        ulonglong2 w1 = *(const ulonglong2*)&sWe[k*MM + m0 + 4];
        #pragma unroll
        for (int i = 0; i < 4; i++) {
            float sv = ss[(r0 + i)*ESS + k];
            unsigned long long sp = pk2(sv, sv);
            fma2(acc[i][0], sp, w0.x);
            fma2(acc[i][1], sp, w0.y);
            fma2(acc[i][2], sp, w1.x);
            fma2(acc[i][3], sp, w1.y);
        }
    }
    float4 be0 = *(const float4*)&b_eslice[m0];
    float4 be1 = *(const float4*)&b_eslice[m0 + 4];
    __syncthreads();
    #pragma unroll
    for (int i = 0; i < 4; i++) {
        float2 a0 = up2(acc[i][0]), a1 = up2(acc[i][1]);
        float2 a2v = up2(acc[i][2]), a3 = up2(acc[i][3]);
        float* d = &ss[(r0 + i)*ESS + m0];
        d[0] = a0.x + be0.x; d[1] = a0.y + be0.y;
        d[2] = a1.x + be0.z; d[3] = a1.y + be0.w;
        d[4] = a2v.x + be1.x; d[5] = a2v.y + be1.y;
        d[6] = a3.x + be1.z; d[7] = a3.y + be1.w;
    }
    __syncthreads();

    // softmax per edge (in place, never leaves smem)
    if (tid < K4_ROWS) {
        float* row = &ss[tid*ESS];
        float mx = -1e30f;
        #pragma unroll
        for (int m = 0; m < MM; m++) mx = fmaxf(mx, row[m]);
        float s = 0.f;
        #pragma unroll
        for (int m = 0; m < MM; m++) {
            float e = __expf(row[m] - mx);
            row[m] = e; s += e;
        }
        float inv = 1.f / s;
        #pragma unroll
        for (int m = 0; m < MM; m++) row[m] *= inv;
    }
    __syncthreads();

    // reductions: enorm[m] = sum_r esw,  es1[m] = sum_r esw * a
    if (tid < MM) {
        float n = 0.f, s1 = 0.f;
        #pragma unroll 4
        for (int r = 0; r < K4_ROWS; r++) {
            float v = ss[r*ESS + tid];
            n += v;
            s1 = fmaf(v, sa[r], s1);
        }
        g_epart[(size_t)blockIdx.x*(2*MM) + tid]      = n;
        g_epart[(size_t)blockIdx.x*(2*MM) + MM + tid] = s1;
    }
}

// ======================= K5: stage-1 Tpart reduction ======================
// grid = JSPLIT * BB*MM = 2048; each block sums 16 of the 128 node-block
// partials for one (b,m), all 256 c.
__global__ void __launch_bounds__(256) k_redT()
{
    int jc = blockIdx.x >> 8;        // 0..7
    int bm = blockIdx.x & 255;       // b*64+m
    int b = bm >> 6, m = bm & 63;
    int tid = threadIdx.x;
    const float* tp = g_Tpart + ((size_t)(b*(NN/K1_ROWS) + jc*16))*(MM*CC)
                              + m*CC + tid;
    float s = 0.f;
    #pragma unroll
    for (int j = 0; j < 16; j++) s += tp[(size_t)j*(MM*CC)];
    g_T2[(size_t)blockIdx.x*CC + tid] = s;
}

// ======================= K6: reduce + finalize ======================
__global__ void __launch_bounds__(256) k_final(const float* __restrict__ W_fx,
                                               const float* __restrict__ b_fx,
                                               const float* __restrict__ W_fedge,
                                               float* __restrict__ out)
{
    int bm = blockIdx.x;
    int b = bm >> 6, m = bm & 63;
    int tid = threadIdx.x;
    __shared__ float Ts[CC];
    __shared__ float red[256];
    __shared__ float s_sn, s_en, s_e1;

    const int nodeBlkPerB = NN / K1_ROWS;   // 128
    const int edgeBlkPerB = EE / K4_ROWS;   // 512

    // reduce T2 (8 pre-reduced rows)
    {
        const float* t2 = g_T2 + (size_t)bm*CC + tid;
        float tv = 0.f;
        #pragma unroll
        for (int jc = 0; jc < JSPLIT; jc++) tv += t2[(size_t)jc*(BB*MM*CC)];
        Ts[tid] = tv;
    }
    // snorm
    red[tid] = (tid < nodeBlkPerB) ? g_npart[(b*nodeBlkPerB + tid)*MM + m] : 0.f;
    __syncthreads();
    for (int s = 128; s > 0; s >>= 1) { if (tid < s) red[tid] += red[tid + s]; __syncthreads(); }
    if (tid == 0) s_sn = red[0];
    __syncthreads();
    // enorm
    red[tid] = g_epart[(size_t)(b*edgeBlkPerB + tid)*(2*MM) + m]
             + g_epart[(size_t)(b*edgeBlkPerB + 256 + tid)*(2*MM) + m];
    __syncthreads();
    for (int s = 128; s > 0; s >>= 1) { if (tid < s) red[tid] += red[tid + s]; __syncthreads(); }
    if (tid == 0) s_en = red[0];
    __syncthreads();
    // es1
    red[tid] = g_epart[(size_t)(b*edgeBlkPerB + tid)*(2*MM) + MM + m]
             + g_epart[(size_t)(b*edgeBlkPerB + 256 + tid)*(2*MM) + MM + m];
    __syncthreads();
    for (int s = 128; s > 0; s >>= 1) { if (tid < s) red[tid] += red[tid + s]; __syncthreads(); }
    if (tid == 0) s_e1 = red[0];
    __syncthreads();

    const float scale = (float)NN / (float)EE;   // 0.25
    float den = s_sn + scale * s_en + 1e-5f;
    float num = 0.f;
    #pragma unroll 8
    for (int k = 0; k < CC; k++) num = fmaf(Ts[k], W_fx[k*CC + tid], num);
    num += s_sn * b_fx[tid] + scale * (s_e1 * W_fedge[tid] + s_en * g_cedge[tid]);
    out[(size_t)bm * CC + tid] = num / den;
}

// ======================= launch ======================
extern "C" void kernel_launch(void* const* d_in, const int* in_sizes, int n_in,
                              void* d_out, int out_size)
{
    const float* x         = (const float*)d_in[0];
    const float* edge_attr = (const float*)d_in[1];
    const int*   edge_idx  = (const int*)  d_in[2];
    const float* W_fx      = (const float*)d_in[3];
    const float* b_fx      = (const float*)d_in[4];
    const float* W_x       = (const float*)d_in[5];
    const float* b_x       = (const float*)d_in[6];
    const float* W_slice   = (const float*)d_in[7];
    const float* b_slice   = (const float*)d_in[8];
    const float* temp_x    = (const float*)d_in[9];
    const float* ph_x      = (const float*)d_in[10];
    const float* W_fedge   = (const float*)d_in[11];
    const float* b_fedge   = (const float*)d_in[12];
    const float* temp_edge = (const float*)d_in[13];
    const float* W_eslice  = (const float*)d_in[14];
    const float* b_eslice  = (const float*)d_in[15];
    const float* ph_edge   = (const float*)d_in[16];
    float* out = (float*)d_out;

    const int smem1 = (CC*MM + K1_ROWS*SXS) * 4;            // 198,656 B
    const int smem4 = (MM*MM + K4_ROWS*ESS + K4_ROWS) * 4;  //  50,176 B
    cudaFuncSetAttribute(k_node, cudaFuncAttributeMaxDynamicSharedMemorySize, smem1);
    cudaFuncSetAttribute(k_edge, cudaFuncAttributeMaxDynamicSharedMemorySize, smem4);

    k_prep<<<MM + 1, 256>>>(W_x, b_x, W_slice, b_slice, temp_x, ph_x,
                            b_fedge, temp_edge, W_eslice, ph_edge);
    k_node<<<K1_GRID, 512, smem1>>>(x, out);
    k_edge<<<K4_GRID, 256, smem4>>>(edge_attr, edge_idx, b_eslice, out);
    k_redT<<<JSPLIT*BB*MM, 256>>>();
    k_final<<<BB*MM, 256>>>(W_fx, b_fx, W_fedge, out);
}

// round 9
// speedup vs baseline: 1.7679x; 1.7679x over previous
#include <cuda_runtime.h>
#include <cuda_bf16.h>
#include <cstdint>

// Problem constants
#define BB 4
#define NN 16384
#define EE 65536
#define CC 256
#define MM 64

// Derived
#define K1_ROWS 128
#define K1_GRID (BB*NN/K1_ROWS)          // 512
#define K4_ROWS 128
#define K4_GRID (BB*EE/K4_ROWS)          // 2048
#define SXS 260                          // padded x-tile stride (words, 16B-aligned rows)
#define LTS 68                           // padded logit-tile stride (words)
#define ESS 65                           // padded edge-tile stride
#define JSPLIT 8                         // Tpart reduction split factor

// ---------- packed fp32x2 helpers (FFMA2 — ptxas never emits this from C++) ----
__device__ __forceinline__ unsigned long long pk2(float lo, float hi) {
    unsigned long long r;
    asm("mov.b64 %0, {%1, %2};" : "=l"(r) : "f"(lo), "f"(hi));
    return r;
}
__device__ __forceinline__ void fma2(unsigned long long& d, unsigned long long a,
                                     unsigned long long b) {
    asm("fma.rn.f32x2 %0, %1, %2, %0;" : "+l"(d) : "l"(a), "l"(b));
}
__device__ __forceinline__ float2 up2(unsigned long long v) {
    float2 r;
    asm("mov.b64 {%0, %1}, %2;" : "=f"(r.x), "=f"(r.y) : "l"(v));
    return r;
}

// -------- device scratch (no allocations allowed) --------
__device__ __align__(16) float g_Wc[CC*MM];            // (W_x @ W_slice)/t_x  [C,M]
__device__ __align__(16) float g_bc[MM];               // ((b_x+ph_x)@W_slice + b_slice)/t_x
__device__ __align__(16) float g_We[MM*MM];            // W_eslice[k,m]/t_e[k]
__device__ __align__(16) float g_cedge[CC];            // b_fedge + ph_edge
__device__ __align__(16) float g_Tpart[(size_t)K1_GRID*MM*CC]; // 32MB partials of sw^T x
__device__ __align__(16) float g_T2[(size_t)JSPLIT*BB*MM*CC];  // 2MB stage-1 reduced
__device__ __align__(16) float g_npart[K1_GRID*MM];    // per-block column sums of sw
__device__ __align__(16) float g_epart[(size_t)K4_GRID*2*MM];  // per-block [enorm(64), es1(64)]

// ======================= K0a: prep We (launch #1) ===========================
__global__ void __launch_bounds__(256) k_prep_e(const float* __restrict__ W_eslice,
                                                const float* __restrict__ temp_edge)
{
    int idx = blockIdx.x * 256 + threadIdx.x;   // 0..4095
    int k = idx >> 6;
    float te = fminf(fmaxf(temp_edge[k], 0.01f), 5.0f);
    g_We[idx] = W_eslice[idx] / te;
}

// ======================= K0b: prep cedge (launch #2) ========================
__global__ void __launch_bounds__(256) k_prep_c(const float* __restrict__ b_fedge,
                                                const float* __restrict__ ph_edge)
{
    int tid = threadIdx.x;
    g_cedge[tid] = b_fedge[tid] + ph_edge[tid];
}

// ======================= K0c: prep Wc/bc (launch #3) ========================
__global__ void __launch_bounds__(256) k_prep_w(
    const float* __restrict__ W_x,  const float* __restrict__ b_x,
    const float* __restrict__ W_slice, const float* __restrict__ b_slice,
    const float* __restrict__ temp_x, const float* __restrict__ ph_x)
{
    int tid = threadIdx.x;
    int mb  = blockIdx.x;
    __shared__ float wsl[CC];
    __shared__ float red[256];
    wsl[tid] = W_slice[tid*MM + mb];
    __syncthreads();
    float tx = fminf(fmaxf(temp_x[mb], 0.01f), 5.0f);
    float itx = 1.0f / tx;
    // Wc column mb (float4 row loads)
    const float4* wxr = (const float4*)(W_x + (size_t)tid*CC);
    float a = 0.f;
    #pragma unroll 8
    for (int k = 0; k < CC/4; k++) {
        float4 w = wxr[k];
        float4 sv = *(const float4*)&wsl[k*4];
        a = fmaf(w.x, sv.x, a); a = fmaf(w.y, sv.y, a);
        a = fmaf(w.z, sv.z, a); a = fmaf(w.w, sv.w, a);
    }
    g_Wc[tid*MM + mb] = a * itx;
    // bc[mb]
    red[tid] = (b_x[tid] + ph_x[tid]) * wsl[tid];
    __syncthreads();
    for (int s = 128; s > 0; s >>= 1) {
        if (tid < s) red[tid] += red[tid + s];
        __syncthreads();
    }
    if (tid == 0) g_bc[mb] = (red[0] + b_slice[mb]) * itx;
}

// ======================= K1: node path (launch #4 — profiled) ========
// Per block: 128 rows. logits GEMM -> softmax -> write slice_weight,
// column sums -> g_npart, partial sw^T x -> g_Tpart. Inner loops use FFMA2.
__global__ void __launch_bounds__(256) k_node(const float* __restrict__ x,
                                              float* __restrict__ out)
{
    extern __shared__ float sm[];
    float* sWc = sm;                 // 16384 floats (64KB)
    float* sx  = sm + CC*MM;         // 128*260 floats
    float* lt  = sm;                 // alias of sWc region after GEMM (128*68 <= 16384)

    int tid = threadIdx.x;
    int r0g = blockIdx.x * K1_ROWS;

    // load Wc (coalesced float4)
    {
        const float4* wg = (const float4*)g_Wc;
        float4* ws = (float4*)sWc;
        #pragma unroll
        for (int i = 0; i < 16; i++) ws[tid + i*256] = wg[tid + i*256];
    }
    // load x tile -> padded smem (row stride 260, 16B-aligned rows)
    {
        const float4* xg = (const float4*)(x + (size_t)r0g*CC);
        #pragma unroll
        for (int i = 0; i < 32; i++) {
            int idx4 = i*256 + tid;
            float4 v = xg[idx4];
            int row = idx4 >> 6, c = (idx4 & 63) * 4;
            *(float4*)&sx[row*SXS + c] = v;
        }
    }
    __syncthreads();

    // ---- logits GEMM: each thread 8 rows x 4 m, packed m-pairs ----
    int tm = tid & 15, tr = tid >> 4;
    int m0 = tm * 4, rb = tr * 8;
    unsigned long long acc[8][2] = {};

    #pragma unroll 4
    for (int c = 0; c < CC; c += 4) {
        ulonglong2 w0 = *(const ulonglong2*)&sWc[(c+0)*MM + m0];
        ulonglong2 w1 = *(const ulonglong2*)&sWc[(c+1)*MM + m0];
        ulonglong2 w2 = *(const ulonglong2*)&sWc[(c+2)*MM + m0];
        ulonglong2 w3 = *(const ulonglong2*)&sWc[(c+3)*MM + m0];
        #pragma unroll
        for (int i = 0; i < 8; i++) {
            float4 xv = *(const float4*)&sx[(rb + i)*SXS + c];
            unsigned long long xp;
            xp = pk2(xv.x, xv.x); fma2(acc[i][0], xp, w0.x); fma2(acc[i][1], xp, w0.y);
            xp = pk2(xv.y, xv.y); fma2(acc[i][0], xp, w1.x); fma2(acc[i][1], xp, w1.y);
            xp = pk2(xv.z, xv.z); fma2(acc[i][0], xp, w2.x); fma2(acc[i][1], xp, w2.y);
            xp = pk2(xv.w, xv.w); fma2(acc[i][0], xp, w3.x); fma2(acc[i][1], xp, w3.y);
        }
    }
    float4 bb = *(const float4*)&g_bc[m0];
    __syncthreads();   // done reading sWc; safe to overwrite as lt
    #pragma unroll
    for (int i = 0; i < 8; i++) {
        float2 a0 = up2(acc[i][0]), a1 = up2(acc[i][1]);
        float* d = &lt[(rb + i)*LTS + m0];
        d[0] = a0.x + bb.x;
        d[1] = a0.y + bb.y;
        d[2] = a1.x + bb.z;
        d[3] = a1.y + bb.w;
    }
    __syncthreads();

    // ---- softmax per row (threads 0..127), write slice_weight ----
    if (tid < K1_ROWS) {
        float* row = &lt[tid*LTS];
        float mx = -1e30f;
        #pragma unroll
        for (int m = 0; m < MM; m++) mx = fmaxf(mx, row[m]);
        float s = 0.f;
        #pragma unroll
        for (int m = 0; m < MM; m++) {
            float e = __expf(row[m] - mx);
            row[m] = e; s += e;
        }
        float inv = 1.f / s;
        float4* og = (float4*)(out + (size_t)BB*MM*CC + (size_t)(r0g + tid)*MM);
        #pragma unroll
        for (int m4 = 0; m4 < 16; m4++) {
            float4 v;
            v.x = row[m4*4+0]*inv; v.y = row[m4*4+1]*inv;
            v.z = row[m4*4+2]*inv; v.w = row[m4*4+3]*inv;
            og[m4] = v;
            row[m4*4+0]=v.x; row[m4*4+1]=v.y; row[m4*4+2]=v.z; row[m4*4+3]=v.w;
        }
    }
    __syncthreads();

    // column sums of sw -> npart
    if (tid < MM) {
        float s = 0.f;
        #pragma unroll 4
        for (int r = 0; r < K1_ROWS; r++) s += lt[r*LTS + tid];
        g_npart[blockIdx.x*MM + tid] = s;
    }

    // ---- partial T = sw^T @ x  (64 x 256), packed m-pairs, 8 warps ----
    int wq = tid >> 5;       // warp id -> m rows wq*8 .. wq*8+7
    int lane = tid & 31;     // c = q*128 + k*32 + lane
    float* tp = g_Tpart + (size_t)blockIdx.x * (MM*CC);
    #pragma unroll
    for (int q = 0; q < 2; q++) {
        unsigned long long a2[4][4] = {};   // [m-pair][k]
        for (int r = 0; r < K1_ROWS; r++) {
            ulonglong2 s0 = *(const ulonglong2*)&lt[r*LTS + wq*8];      // (m0,m1),(m2,m3)
            ulonglong2 s1 = *(const ulonglong2*)&lt[r*LTS + wq*8 + 4];  // (m4,m5),(m6,m7)
            #pragma unroll
            for (int k = 0; k < 4; k++) {
                float xv = sx[r*SXS + q*128 + k*32 + lane];
                unsigned long long xp = pk2(xv, xv);
                fma2(a2[0][k], s0.x, xp);
                fma2(a2[1][k], s0.y, xp);
                fma2(a2[2][k], s1.x, xp);
                fma2(a2[3][k], s1.y, xp);
            }
        }
        #pragma unroll
        for (int jp = 0; jp < 4; jp++)
            #pragma unroll
            for (int k = 0; k < 4; k++) {
                float2 v = up2(a2[jp][k]);
                int cc = q*128 + k*32 + lane;
                tp[(wq*8 + jp*2    )*CC + cc] = v.x;
                tp[(wq*8 + jp*2 + 1)*CC + cc] = v.y;
            }
    }
}

// ======================= K4: edge path ======================
__global__ void __launch_bounds__(256) k_edge(const float* __restrict__ edge_attr,
                                              const int*   __restrict__ edge_idx,
                                              const float* __restrict__ b_eslice,
                                              const float* __restrict__ out_ro)
{
    extern __shared__ float sm[];
    float* sWe = sm;                  // 4096
    float* ss  = sm + MM*MM;          // 128*65
    float* sa  = ss + K4_ROWS*ESS;    // 128

    int tid = threadIdx.x;
    int eb  = blockIdx.x * K4_ROWS;
    int b   = eb >> 16;               // E = 65536
    const float* swb = out_ro + (size_t)BB*MM*CC + (size_t)b*NN*MM;

    // load We
    {
        const float4* s = (const float4*)g_We;
        float4* d = (float4*)sWe;
        #pragma unroll
        for (int i = 0; i < 4; i++) d[tid + i*256] = s[tid + i*256];
    }
    if (tid < K4_ROWS) sa[tid] = edge_attr[eb + tid];

    // gather + sum (2 threads per edge)
    {
        int r = tid >> 1, half = tid & 1;
        int i0 = edge_idx[(size_t)(eb + r)*2 + 0];
        int i1 = edge_idx[(size_t)(eb + r)*2 + 1];
        const float4* p0 = (const float4*)(swb + (size_t)i0*MM) + half*8;
        const float4* p1 = (const float4*)(swb + (size_t)i1*MM) + half*8;
        float* d = &ss[r*ESS + half*32];
        #pragma unroll
        for (int j = 0; j < 8; j++) {
            float4 a = p0[j], c = p1[j];
            d[j*4+0] = a.x + c.x; d[j*4+1] = a.y + c.y;
            d[j*4+2] = a.z + c.z; d[j*4+3] = a.w + c.w;
        }
    }
    __syncthreads();

    // GEMM: each thread 4 rows x 8 m, packed m-pairs
    int tm = tid & 7, trr = tid >> 3;
    int m0 = tm * 8, r0 = trr * 4;
    unsigned long long acc[4][4] = {};

    #pragma unroll 4
    for (int k = 0; k < MM; k++) {
        ulonglong2 w0 = *(const ulonglong2*)&sWe[k*MM + m0];
        ulonglong2 w1 = *(const ulonglong2*)&sWe[k*MM + m0 + 4];
        #pragma unroll
        for (int i = 0; i < 4; i++) {
            float sv = ss[(r0 + i)*ESS + k];
            unsigned long long sp = pk2(sv, sv);
            fma2(acc[i][0], sp, w0.x);
            fma2(acc[i][1], sp, w0.y);
            fma2(acc[i][2], sp, w1.x);
            fma2(acc[i][3], sp, w1.y);
        }
    }
    float4 be0 = *(const float4*)&b_eslice[m0];
    float4 be1 = *(const float4*)&b_eslice[m0 + 4];
    __syncthreads();
    #pragma unroll
    for (int i = 0; i < 4; i++) {
        float2 a0 = up2(acc[i][0]), a1 = up2(acc[i][1]);
        float2 a2v = up2(acc[i][2]), a3 = up2(acc[i][3]);
        float* d = &ss[(r0 + i)*ESS + m0];
        d[0] = a0.x + be0.x; d[1] = a0.y + be0.y;
        d[2] = a1.x + be0.z; d[3] = a1.y + be0.w;
        d[4] = a2v.x + be1.x; d[5] = a2v.y + be1.y;
        d[6] = a3.x + be1.z; d[7] = a3.y + be1.w;
    }
    __syncthreads();

    // softmax per edge (in place, never leaves smem)
    if (tid < K4_ROWS) {
        float* row = &ss[tid*ESS];
        float mx = -1e30f;
        #pragma unroll
        for (int m = 0; m < MM; m++) mx = fmaxf(mx, row[m]);
        float s = 0.f;
        #pragma unroll
        for (int m = 0; m < MM; m++) {
            float e = __expf(row[m] - mx);
            row[m] = e; s += e;
        }
        float inv = 1.f / s;
        #pragma unroll
        for (int m = 0; m < MM; m++) row[m] *= inv;
    }
    __syncthreads();

    // reductions: enorm[m] = sum_r esw,  es1[m] = sum_r esw * a
    if (tid < MM) {
        float n = 0.f, s1 = 0.f;
        #pragma unroll 4
        for (int r = 0; r < K4_ROWS; r++) {
            float v = ss[r*ESS + tid];
            n += v;
            s1 = fmaf(v, sa[r], s1);
        }
        g_epart[(size_t)blockIdx.x*(2*MM) + tid]      = n;
        g_epart[(size_t)blockIdx.x*(2*MM) + MM + tid] = s1;
    }
}

// ======================= K5: stage-1 Tpart reduction (verified 10us) ======
__global__ void __launch_bounds__(256) k_redT()
{
    int jc = blockIdx.x >> 8;        // 0..7
    int bm = blockIdx.x & 255;       // b*64+m
    int b = bm >> 6, m = bm & 63;
    int tid = threadIdx.x;
    const float* tp = g_Tpart + ((size_t)(b*(NN/K1_ROWS) + jc*16))*(MM*CC)
                              + m*CC + tid;
    float s = 0.f;
    #pragma unroll
    for (int j = 0; j < 16; j++) s += tp[(size_t)j*(MM*CC)];
    g_T2[(size_t)blockIdx.x*CC + tid] = s;
}

// ======================= K6: reduce + finalize ======================
__global__ void __launch_bounds__(256) k_final(const float* __restrict__ W_fx,
                                               const float* __restrict__ b_fx,
                                               const float* __restrict__ W_fedge,
                                               float* __restrict__ out)
{
    int bm = blockIdx.x;
    int b = bm >> 6, m = bm & 63;
    int tid = threadIdx.x;
    __shared__ float Ts[CC];
    __shared__ float red[256];
    __shared__ float s_sn, s_en, s_e1;

    const int nodeBlkPerB = NN / K1_ROWS;   // 128
    const int edgeBlkPerB = EE / K4_ROWS;   // 512

    // reduce T2 (8 pre-reduced rows)
    {
        const float* t2 = g_T2 + (size_t)bm*CC + tid;
        float tv = 0.f;
        #pragma unroll
        for (int jc = 0; jc < JSPLIT; jc++) tv += t2[(size_t)jc*(BB*MM*CC)];
        Ts[tid] = tv;
    }
    // snorm
    red[tid] = (tid < nodeBlkPerB) ? g_npart[(b*nodeBlkPerB + tid)*MM + m] : 0.f;
    __syncthreads();
    for (int s = 128; s > 0; s >>= 1) { if (tid < s) red[tid] += red[tid + s]; __syncthreads(); }
    if (tid == 0) s_sn = red[0];
    __syncthreads();
    // enorm
    red[tid] = g_epart[(size_t)(b*edgeBlkPerB + tid)*(2*MM) + m]
             + g_epart[(size_t)(b*edgeBlkPerB + 256 + tid)*(2*MM) + m];
    __syncthreads();
    for (int s = 128; s > 0; s >>= 1) { if (tid < s) red[tid] += red[tid + s]; __syncthreads(); }
    if (tid == 0) s_en = red[0];
    __syncthreads();
    // es1
    red[tid] = g_epart[(size_t)(b*edgeBlkPerB + tid)*(2*MM) + MM + m]
             + g_epart[(size_t)(b*edgeBlkPerB + 256 + tid)*(2*MM) + MM + m];
    __syncthreads();
    for (int s = 128; s > 0; s >>= 1) { if (tid < s) red[tid] += red[tid + s]; __syncthreads(); }
    if (tid == 0) s_e1 = red[0];
    __syncthreads();

    const float scale = (float)NN / (float)EE;   // 0.25
    float den = s_sn + scale * s_en + 1e-5f;
    float num = 0.f;
    #pragma unroll 8
    for (int k = 0; k < CC; k++) num = fmaf(Ts[k], W_fx[k*CC + tid], num);
    num += s_sn * b_fx[tid] + scale * (s_e1 * W_fedge[tid] + s_en * g_cedge[tid]);
    out[(size_t)bm * CC + tid] = num / den;
}

// ======================= launch ======================
extern "C" void kernel_launch(void* const* d_in, const int* in_sizes, int n_in,
                              void* d_out, int out_size)
{
    const float* x         = (const float*)d_in[0];
    const float* edge_attr = (const float*)d_in[1];
    const int*   edge_idx  = (const int*)  d_in[2];
    const float* W_fx      = (const float*)d_in[3];
    const float* b_fx      = (const float*)d_in[4];
    const float* W_x       = (const float*)d_in[5];
    const float* b_x       = (const float*)d_in[6];
    const float* W_slice   = (const float*)d_in[7];
    const float* b_slice   = (const float*)d_in[8];
    const float* temp_x    = (const float*)d_in[9];
    const float* ph_x      = (const float*)d_in[10];
    const float* W_fedge   = (const float*)d_in[11];
    const float* b_fedge   = (const float*)d_in[12];
    const float* temp_edge = (const float*)d_in[13];
    const float* W_eslice  = (const float*)d_in[14];
    const float* b_eslice  = (const float*)d_in[15];
    const float* ph_edge   = (const float*)d_in[16];
    float* out = (float*)d_out;

    const int smem1 = (CC*MM + K1_ROWS*SXS) * 4;            // 198,656 B
    const int smem4 = (MM*MM + K4_ROWS*ESS + K4_ROWS) * 4;  //  50,176 B
    cudaFuncSetAttribute(k_node, cudaFuncAttributeMaxDynamicSharedMemorySize, smem1);
    cudaFuncSetAttribute(k_edge, cudaFuncAttributeMaxDynamicSharedMemorySize, smem4);

    // Launch order chosen so k_node is the 4th launch (ncu capture window).
    k_prep_e<<<16, 256>>>(W_eslice, temp_edge);                      // #1
    k_prep_c<<<1, 256>>>(b_fedge, ph_edge);                          // #2
    k_prep_w<<<MM, 256>>>(W_x, b_x, W_slice, b_slice, temp_x, ph_x); // #3
    k_node<<<K1_GRID, 256, smem1>>>(x, out);                         // #4
    k_edge<<<K4_GRID, 256, smem4>>>(edge_attr, edge_idx, b_eslice, out);
    k_redT<<<JSPLIT*BB*MM, 256>>>();
    k_final<<<BB*MM, 256>>>(W_fx, b_fx, W_fedge, out);
}

// round 13
// speedup vs baseline: 1.9753x; 1.1174x over previous
#include <cuda_runtime.h>
#include <cuda_bf16.h>
#include <cstdint>

// Problem constants
#define BB 4
#define NN 16384
#define EE 65536
#define CC 256
#define MM 64

// Derived
#define K1_ROWS 128
#define K1_GRID (BB*NN/K1_ROWS)          // 512
#define K4_ROWS 128
#define K4_GRID (BB*EE/K4_ROWS)          // 2048
#define SXS 260                          // padded x-tile stride (words, 16B-aligned rows)
#define LTS 68                           // padded logit-tile stride (words)
#define ESS 65                           // padded edge-tile stride
#define JSPLIT 8                         // Tpart reduction split factor

// ---------- packed fp32x2 helpers (FFMA2 — ptxas never emits this from C++) ----
__device__ __forceinline__ unsigned long long pk2(float lo, float hi) {
    unsigned long long r;
    asm("mov.b64 %0, {%1, %2};" : "=l"(r) : "f"(lo), "f"(hi));
    return r;
}
__device__ __forceinline__ void fma2(unsigned long long& d, unsigned long long a,
                                     unsigned long long b) {
    asm("fma.rn.f32x2 %0, %1, %2, %0;" : "+l"(d) : "l"(a), "l"(b));
}
__device__ __forceinline__ float2 up2(unsigned long long v) {
    float2 r;
    asm("mov.b64 {%0, %1}, %2;" : "=f"(r.x), "=f"(r.y) : "l"(v));
    return r;
}

// -------- device scratch (no allocations allowed) --------
__device__ __align__(16) float g_Wc[CC*MM];            // (W_x @ W_slice)/t_x  [C,M]
__device__ __align__(16) float g_bc[MM];               // ((b_x+ph_x)@W_slice + b_slice)/t_x
__device__ __align__(16) float g_We[MM*MM];            // W_eslice[k,m]/t_e[k]
__device__ __align__(16) float g_cedge[CC];            // b_fedge + ph_edge
__device__ __align__(16) float g_Z[(size_t)BB*NN*MM];  // 16MB  Z = sw @ We per node
__device__ __align__(16) float g_Tpart[(size_t)K1_GRID*MM*CC]; // 32MB partials of sw^T x
__device__ __align__(16) float g_T2[(size_t)JSPLIT*BB*MM*CC];  // 2MB stage-1 reduced
__device__ __align__(16) float g_npart[K1_GRID*MM];    // per-block column sums of sw
__device__ __align__(16) float g_epart[(size_t)K4_GRID*2*MM];  // per-block [enorm(64), es1(64)]

// ======================= K0a: prep We (launch #1) ===========================
__global__ void __launch_bounds__(256) k_prep_e(const float* __restrict__ W_eslice,
                                                const float* __restrict__ temp_edge)
{
    int idx = blockIdx.x * 256 + threadIdx.x;   // 0..4095
    int k = idx >> 6;
    float te = fminf(fmaxf(temp_edge[k], 0.01f), 5.0f);
    g_We[idx] = W_eslice[idx] / te;
}

// ======================= K0b: prep cedge (launch #2) ========================
__global__ void __launch_bounds__(256) k_prep_c(const float* __restrict__ b_fedge,
                                                const float* __restrict__ ph_edge)
{
    int tid = threadIdx.x;
    g_cedge[tid] = b_fedge[tid] + ph_edge[tid];
}

// ======================= K0c: prep Wc/bc (launch #3) ========================
__global__ void __launch_bounds__(256) k_prep_w(
    const float* __restrict__ W_x,  const float* __restrict__ b_x,
    const float* __restrict__ W_slice, const float* __restrict__ b_slice,
    const float* __restrict__ temp_x, const float* __restrict__ ph_x)
{
    int tid = threadIdx.x;
    int mb  = blockIdx.x;
    __shared__ float wsl[CC];
    __shared__ float red[256];
    wsl[tid] = W_slice[tid*MM + mb];
    __syncthreads();
    float tx = fminf(fmaxf(temp_x[mb], 0.01f), 5.0f);
    float itx = 1.0f / tx;
    const float4* wxr = (const float4*)(W_x + (size_t)tid*CC);
    float a = 0.f;
    #pragma unroll 8
    for (int k = 0; k < CC/4; k++) {
        float4 w = wxr[k];
        float4 sv = *(const float4*)&wsl[k*4];
        a = fmaf(w.x, sv.x, a); a = fmaf(w.y, sv.y, a);
        a = fmaf(w.z, sv.z, a); a = fmaf(w.w, sv.w, a);
    }
    g_Wc[tid*MM + mb] = a * itx;
    red[tid] = (b_x[tid] + ph_x[tid]) * wsl[tid];
    __syncthreads();
    for (int s = 128; s > 0; s >>= 1) {
        if (tid < s) red[tid] += red[tid + s];
        __syncthreads();
    }
    if (tid == 0) g_bc[mb] = (red[0] + b_slice[mb]) * itx;
}

// ======================= K1: node path (512 threads, launch #4) ========
// Per block: 128 rows. logits GEMM (4r x 4m tile) -> softmax -> write
// slice_weight; Z = sw@We -> g_Z; column sums -> g_npart; sw^T x -> g_Tpart.
__global__ void __launch_bounds__(512) k_node(const float* __restrict__ x,
                                              float* __restrict__ out)
{
    extern __shared__ float sm[];
    float* sWc = sm;                         // 16384 floats (64KB)
    float* sx  = sm + CC*MM;                 // 128*260 floats (130KB)
    float* sWe = sm + CC*MM + K1_ROWS*SXS;   // 4096 floats (16KB)
    float* lt  = sm;                         // alias of sWc after GEMM (128*68 = 8704)

    int tid = threadIdx.x;
    int r0g = blockIdx.x * K1_ROWS;

    // load Wc (4096 float4) + We (1024 float4)
    {
        const float4* wg = (const float4*)g_Wc;
        float4* ws = (float4*)sWc;
        #pragma unroll
        for (int i = 0; i < 8; i++) ws[tid + i*512] = wg[tid + i*512];
        const float4* eg = (const float4*)g_We;
        float4* es = (float4*)sWe;
        #pragma unroll
        for (int i = 0; i < 2; i++) es[tid + i*512] = eg[tid + i*512];
    }
    // load x tile (8192 float4)
    {
        const float4* xg = (const float4*)(x + (size_t)r0g*CC);
        #pragma unroll
        for (int i = 0; i < 16; i++) {
            int idx4 = i*512 + tid;
            float4 v = xg[idx4];
            int row = idx4 >> 6, c = (idx4 & 63) * 4;
            *(float4*)&sx[row*SXS + c] = v;
        }
    }
    __syncthreads();

    // ---- logits GEMM: each thread 4 rows x 4 m ----
    int tm = tid & 15, tr = tid >> 4;    // tr 0..31
    int m0 = tm * 4, rb = tr * 4;
    unsigned long long acc[4][2] = {};

    #pragma unroll 4
    for (int c = 0; c < CC; c += 4) {
        ulonglong2 w0 = *(const ulonglong2*)&sWc[(c+0)*MM + m0];
        ulonglong2 w1 = *(const ulonglong2*)&sWc[(c+1)*MM + m0];
        ulonglong2 w2 = *(const ulonglong2*)&sWc[(c+2)*MM + m0];
        ulonglong2 w3 = *(const ulonglong2*)&sWc[(c+3)*MM + m0];
        #pragma unroll
        for (int i = 0; i < 4; i++) {
            float4 xv = *(const float4*)&sx[(rb + i)*SXS + c];
            unsigned long long xp;
            xp = pk2(xv.x, xv.x); fma2(acc[i][0], xp, w0.x); fma2(acc[i][1], xp, w0.y);
            xp = pk2(xv.y, xv.y); fma2(acc[i][0], xp, w1.x); fma2(acc[i][1], xp, w1.y);
            xp = pk2(xv.z, xv.z); fma2(acc[i][0], xp, w2.x); fma2(acc[i][1], xp, w2.y);
            xp = pk2(xv.w, xv.w); fma2(acc[i][0], xp, w3.x); fma2(acc[i][1], xp, w3.y);
        }
    }
    float4 bb = *(const float4*)&g_bc[m0];
    __syncthreads();   // done reading sWc; region becomes lt
    #pragma unroll
    for (int i = 0; i < 4; i++) {
        float2 a0 = up2(acc[i][0]), a1 = up2(acc[i][1]);
        *(float4*)&lt[(rb + i)*LTS + m0] =
            make_float4(a0.x + bb.x, a0.y + bb.y, a1.x + bb.z, a1.y + bb.w);
    }
    __syncthreads();

    // ---- softmax per row (threads 0..127), write slice_weight ----
    if (tid < K1_ROWS) {
        float* row = &lt[tid*LTS];
        float mx = -1e30f;
        #pragma unroll
        for (int m = 0; m < MM; m++) mx = fmaxf(mx, row[m]);
        float s = 0.f;
        #pragma unroll
        for (int m = 0; m < MM; m++) {
            float e = __expf(row[m] - mx);
            row[m] = e; s += e;
        }
        float inv = 1.f / s;
        float4* og = (float4*)(out + (size_t)BB*MM*CC + (size_t)(r0g + tid)*MM);
        #pragma unroll
        for (int m4 = 0; m4 < 16; m4++) {
            float4 v;
            v.x = row[m4*4+0]*inv; v.y = row[m4*4+1]*inv;
            v.z = row[m4*4+2]*inv; v.w = row[m4*4+3]*inv;
            og[m4] = v;
            row[m4*4+0]=v.x; row[m4*4+1]=v.y; row[m4*4+2]=v.z; row[m4*4+3]=v.w;
        }
    }
    __syncthreads();

    // column sums of sw -> npart
    if (tid < MM) {
        float s = 0.f;
        #pragma unroll 4
        for (int r = 0; r < K1_ROWS; r++) s += lt[r*LTS + tid];
        g_npart[blockIdx.x*MM + tid] = s;
    }

    // ---- Z = sw @ We  (128 x 64), same 4r x 4m tiling ----
    {
        unsigned long long zacc[4][2] = {};
        #pragma unroll 4
        for (int k = 0; k < MM; k++) {
            ulonglong2 wz = *(const ulonglong2*)&sWe[k*MM + m0];
            #pragma unroll
            for (int i = 0; i < 4; i++) {
                float sv = lt[(rb + i)*LTS + k];
                unsigned long long sp = pk2(sv, sv);
                fma2(zacc[i][0], sp, wz.x);
                fma2(zacc[i][1], sp, wz.y);
            }
        }
        float* zb = g_Z + (size_t)r0g * MM;
        #pragma unroll
        for (int i = 0; i < 4; i++) {
            float2 a0 = up2(zacc[i][0]), a1 = up2(zacc[i][1]);
            *(float4*)&zb[(size_t)(rb + i)*MM + m0] = make_float4(a0.x, a0.y, a1.x, a1.y);
        }
    }

    // ---- partial T = sw^T @ x  (64 x 256), 16 warps x 4 m-rows ----
    int wq = tid >> 5, lane = tid & 31;
    int mb4 = wq * 4;
    float* tp = g_Tpart + (size_t)blockIdx.x * (MM*CC);
    #pragma unroll
    for (int q = 0; q < 2; q++) {
        unsigned long long a2[2][4] = {};   // [m-pair][k]
        for (int r = 0; r < K1_ROWS; r++) {
            ulonglong2 s0 = *(const ulonglong2*)&lt[r*LTS + mb4];  // (m0,m1),(m2,m3)
            #pragma unroll
            for (int k = 0; k < 4; k++) {
                float xv = sx[r*SXS + q*128 + k*32 + lane];
                unsigned long long xp = pk2(xv, xv);
                fma2(a2[0][k], s0.x, xp);
                fma2(a2[1][k], s0.y, xp);
            }
        }
        #pragma unroll
        for (int jp = 0; jp < 2; jp++)
            #pragma unroll
            for (int k = 0; k < 4; k++) {
                float2 v = up2(a2[jp][k]);
                int cc = q*128 + k*32 + lane;
                tp[(mb4 + jp*2    )*CC + cc] = v.x;
                tp[(mb4 + jp*2 + 1)*CC + cc] = v.y;
            }
    }
}

// ======================= K4: edge path (GEMM-free) ======================
// e_logits[e] = Z[i0] + Z[i1] + b_eslice  (linearity of the edge GEMM).
// Gather Z rows, add, softmax(+bias), per-block reductions. No We, no GEMM.
__global__ void __launch_bounds__(256) k_edge(const float* __restrict__ edge_attr,
                                              const int*   __restrict__ edge_idx,
                                              const float* __restrict__ b_eslice)
{
    __shared__ float ss[K4_ROWS*ESS];   // 128*65
    __shared__ float sa[K4_ROWS];
    __shared__ float sbe[MM];

    int tid = threadIdx.x;
    int eb  = blockIdx.x * K4_ROWS;
    int b   = eb >> 16;               // E = 65536
    const float* zb = g_Z + (size_t)b*NN*MM;

    if (tid < 16) *(float4*)&sbe[tid*4] = *(const float4*)&b_eslice[tid*4];
    if (tid < K4_ROWS) sa[tid] = edge_attr[eb + tid];

    // gather + sum (2 threads per edge, 8 independent float4 pairs each)
    {
        int r = tid >> 1, half = tid & 1;
        int i0 = edge_idx[(size_t)(eb + r)*2 + 0];
        int i1 = edge_idx[(size_t)(eb + r)*2 + 1];
        const float4* p0 = (const float4*)(zb + (size_t)i0*MM) + half*8;
        const float4* p1 = (const float4*)(zb + (size_t)i1*MM) + half*8;
        float* d = &ss[r*ESS + half*32];
        #pragma unroll
        for (int j = 0; j < 8; j++) {
            float4 a = p0[j], c = p1[j];
            d[j*4+0] = a.x + c.x; d[j*4+1] = a.y + c.y;
            d[j*4+2] = a.z + c.z; d[j*4+3] = a.w + c.w;
        }
    }
    __syncthreads();

    // softmax per edge (bias folded in; stays in smem)
    if (tid < K4_ROWS) {
        float* row = &ss[tid*ESS];
        float mx = -1e30f;
        #pragma unroll
        for (int m = 0; m < MM; m++) mx = fmaxf(mx, row[m] + sbe[m]);
        float s = 0.f;
        #pragma unroll
        for (int m = 0; m < MM; m++) {
            float e = __expf(row[m] + sbe[m] - mx);
            row[m] = e; s += e;
        }
        float inv = 1.f / s;
        #pragma unroll
        for (int m = 0; m < MM; m++) row[m] *= inv;
    }
    __syncthreads();

    // reductions: enorm[m] = sum_r esw,  es1[m] = sum_r esw * a
    if (tid < MM) {
        float n = 0.f, s1 = 0.f;
        #pragma unroll 4
        for (int r = 0; r < K4_ROWS; r++) {
            float v = ss[r*ESS + tid];
            n += v;
            s1 = fmaf(v, sa[r], s1);
        }
        g_epart[(size_t)blockIdx.x*(2*MM) + tid]      = n;
        g_epart[(size_t)blockIdx.x*(2*MM) + MM + tid] = s1;
    }
}

// ======================= K5: stage-1 Tpart reduction (verified 10us) ======
__global__ void __launch_bounds__(256) k_redT()
{
    int jc = blockIdx.x >> 8;        // 0..7
    int bm = blockIdx.x & 255;       // b*64+m
    int b = bm >> 6, m = bm & 63;
    int tid = threadIdx.x;
    const float* tp = g_Tpart + ((size_t)(b*(NN/K1_ROWS) + jc*16))*(MM*CC)
                              + m*CC + tid;
    float s = 0.f;
    #pragma unroll
    for (int j = 0; j < 16; j++) s += tp[(size_t)j*(MM*CC)];
    g_T2[(size_t)blockIdx.x*CC + tid] = s;
}

// ======================= K6: reduce + finalize ======================
__global__ void __launch_bounds__(256) k_final(const float* __restrict__ W_fx,
                                               const float* __restrict__ b_fx,
                                               const float* __restrict__ W_fedge,
                                               float* __restrict__ out)
{
    int bm = blockIdx.x;
    int b = bm >> 6, m = bm & 63;
    int tid = threadIdx.x;
    __shared__ float Ts[CC];
    __shared__ float red[256];
    __shared__ float s_sn, s_en, s_e1;

    const int nodeBlkPerB = NN / K1_ROWS;   // 128
    const int edgeBlkPerB = EE / K4_ROWS;   // 512

    // reduce T2 (8 pre-reduced rows)
    {
        const float* t2 = g_T2 + (size_t)bm*CC + tid;
        float tv = 0.f;
        #pragma unroll
        for (int jc = 0; jc < JSPLIT; jc++) tv += t2[(size_t)jc*(BB*MM*CC)];
        Ts[tid] = tv;
    }
    // snorm
    red[tid] = (tid < nodeBlkPerB) ? g_npart[(b*nodeBlkPerB + tid)*MM + m] : 0.f;
    __syncthreads();
    for (int s = 128; s > 0; s >>= 1) { if (tid < s) red[tid] += red[tid + s]; __syncthreads(); }
    if (tid == 0) s_sn = red[0];
    __syncthreads();
    // enorm
    red[tid] = g_epart[(size_t)(b*edgeBlkPerB + tid)*(2*MM) + m]
             + g_epart[(size_t)(b*edgeBlkPerB + 256 + tid)*(2*MM) + m];
    __syncthreads();
    for (int s = 128; s > 0; s >>= 1) { if (tid < s) red[tid] += red[tid + s]; __syncthreads(); }
    if (tid == 0) s_en = red[0];
    __syncthreads();
    // es1
    red[tid] = g_epart[(size_t)(b*edgeBlkPerB + tid)*(2*MM) + MM + m]
             + g_epart[(size_t)(b*edgeBlkPerB + 256 + tid)*(2*MM) + MM + m];
    __syncthreads();
    for (int s = 128; s > 0; s >>= 1) { if (tid < s) red[tid] += red[tid + s]; __syncthreads(); }
    if (tid == 0) s_e1 = red[0];
    __syncthreads();

    const float scale = (float)NN / (float)EE;   // 0.25
    float den = s_sn + scale * s_en + 1e-5f;
    float num = 0.f;
    #pragma unroll 8
    for (int k = 0; k < CC; k++) num = fmaf(Ts[k], W_fx[k*CC + tid], num);
    num += s_sn * b_fx[tid] + scale * (s_e1 * W_fedge[tid] + s_en * g_cedge[tid]);
    out[(size_t)bm * CC + tid] = num / den;
}

// ======================= launch ======================
extern "C" void kernel_launch(void* const* d_in, const int* in_sizes, int n_in,
                              void* d_out, int out_size)
{
    const float* x         = (const float*)d_in[0];
    const float* edge_attr = (const float*)d_in[1];
    const int*   edge_idx  = (const int*)  d_in[2];
    const float* W_fx      = (const float*)d_in[3];
    const float* b_fx      = (const float*)d_in[4];
    const float* W_x       = (const float*)d_in[5];
    const float* b_x       = (const float*)d_in[6];
    const float* W_slice   = (const float*)d_in[7];
    const float* b_slice   = (const float*)d_in[8];
    const float* temp_x    = (const float*)d_in[9];
    const float* ph_x      = (const float*)d_in[10];
    const float* W_fedge   = (const float*)d_in[11];
    const float* b_fedge   = (const float*)d_in[12];
    const float* temp_edge = (const float*)d_in[13];
    const float* W_eslice  = (const float*)d_in[14];
    const float* b_eslice  = (const float*)d_in[15];
    const float* ph_edge   = (const float*)d_in[16];
    float* out = (float*)d_out;

    const int smem1 = (CC*MM + K1_ROWS*SXS + MM*MM) * 4;    // 215,040 B
    cudaFuncSetAttribute(k_node, cudaFuncAttributeMaxDynamicSharedMemorySize, smem1);

    // Launch order: k_node is the 4th launch (ncu capture window).
    k_prep_e<<<16, 256>>>(W_eslice, temp_edge);                      // #1
    k_prep_c<<<1, 256>>>(b_fedge, ph_edge);                          // #2
    k_prep_w<<<MM, 256>>>(W_x, b_x, W_slice, b_slice, temp_x, ph_x); // #3
    k_node<<<K1_GRID, 512, smem1>>>(x, out);                         // #4
    k_edge<<<K4_GRID, 256>>>(edge_attr, edge_idx, b_eslice);
    k_redT<<<JSPLIT*BB*MM, 256>>>();
    k_final<<<BB*MM, 256>>>(W_fx, b_fx, W_fedge, out);
}